// round 1
// baseline (speedup 1.0000x reference)
#include <cuda_runtime.h>

#define D_MODEL 512
#define KEY_DIM 128
#define BS_N 16
#define CTX_PER 1024
#define ARGS_PER 32
#define N_ARGS (BS_N * ARGS_PER)      /* 512  */
#define N_CTX  (BS_N * CTX_PER)       /* 16384 */
#define P_TOT  (N_ARGS * CTX_PER)     /* 524288 */

// Scratch (allocation-free rule: device globals)
__device__ float g_Qp[N_ARGS * D_MODEL];   // Qp[r,d] = sum_k arg[r,k] * W[d,k]
__device__ float g_qb[N_ARGS];             // qb[r]   = arg[r,:] . b

// ---------------------------------------------------------------------------
// Kernel A: Qp = arg_values @ W^T    (M=512, N=512, K=128)
// 64x64 tile, 256 threads, 4x4 microtile, transposed smem [k][row].
// ---------------------------------------------------------------------------
__global__ __launch_bounds__(256) void qp_kernel(const float* __restrict__ A,
                                                 const float* __restrict__ Wm) {
    __shared__ __align__(16) float As[32][68];
    __shared__ __align__(16) float Bs[32][68];
    const int r0 = blockIdx.y * 64;
    const int d0 = blockIdx.x * 64;
    const int tid = threadIdx.x;
    const int ty = tid >> 4, tx = tid & 15;

    float acc[4][4] = {};

    for (int k0 = 0; k0 < KEY_DIM; k0 += 32) {
        #pragma unroll
        for (int j = 0; j < 2; j++) {
            int id  = tid + j * 256;        // 0..511
            int row = id >> 3;              // 0..63
            int kq  = (id & 7) * 4;         // 0..28
            float4 va = *(const float4*)(A  + (size_t)(r0 + row) * KEY_DIM + k0 + kq);
            float4 vb = *(const float4*)(Wm + (size_t)(d0 + row) * KEY_DIM + k0 + kq);
            As[kq + 0][row] = va.x; As[kq + 1][row] = va.y;
            As[kq + 2][row] = va.z; As[kq + 3][row] = va.w;
            Bs[kq + 0][row] = vb.x; Bs[kq + 1][row] = vb.y;
            Bs[kq + 2][row] = vb.z; Bs[kq + 3][row] = vb.w;
        }
        __syncthreads();
        #pragma unroll
        for (int k = 0; k < 32; k++) {
            float4 a = *(const float4*)&As[k][ty * 4];
            float4 c = *(const float4*)&Bs[k][tx * 4];
            float av[4] = {a.x, a.y, a.z, a.w};
            float cv[4] = {c.x, c.y, c.z, c.w};
            #pragma unroll
            for (int i = 0; i < 4; i++)
                #pragma unroll
                for (int jj = 0; jj < 4; jj++)
                    acc[i][jj] = fmaf(av[i], cv[jj], acc[i][jj]);
        }
        __syncthreads();
    }

    #pragma unroll
    for (int i = 0; i < 4; i++) {
        float4 v = make_float4(acc[i][0], acc[i][1], acc[i][2], acc[i][3]);
        *(float4*)(g_Qp + (size_t)(r0 + ty * 4 + i) * D_MODEL + d0 + tx * 4) = v;
    }
}

// ---------------------------------------------------------------------------
// Kernel A2: qb[r] = arg[r,:] . b
// ---------------------------------------------------------------------------
__global__ void qb_kernel(const float* __restrict__ A, const float* __restrict__ b) {
    int r = blockIdx.x * blockDim.x + threadIdx.x;
    if (r < N_ARGS) {
        float s = 0.f;
        #pragma unroll
        for (int k = 0; k < KEY_DIM / 4; k++) {
            float4 a  = *(const float4*)(A + (size_t)r * KEY_DIM + 4 * k);
            float4 bb = *(const float4*)(b + 4 * k);
            s = fmaf(a.x, bb.x, s); s = fmaf(a.y, bb.y, s);
            s = fmaf(a.z, bb.z, s); s = fmaf(a.w, bb.w, s);
        }
        g_qb[r] = s;
    }
}

// ---------------------------------------------------------------------------
// Kernel B: per state s: logits_s[32,1024] = Qp_s[32,512] @ C_s[1024,512]^T + qb
// Block = one (state, 64-col) tile -> 16 x 16 = 256 blocks, 128 threads,
// 4x4 microtile, K chunked by 32 with transposed smem.
// Also writes the rows plane (rows[p] = global arg row) if requested.
// ---------------------------------------------------------------------------
__global__ __launch_bounds__(128) void logits_kernel(const float* __restrict__ C,
                                                     float* __restrict__ out_logits,
                                                     float* __restrict__ out_rows) {
    __shared__ __align__(16) float Qs[32][36];
    __shared__ __align__(16) float Cs[32][68];
    const int s  = blockIdx.y;              // proof state
    const int c0 = blockIdx.x * 64;         // local ctx column tile
    const int tid = threadIdx.x;
    const int ty = tid >> 4, tx = tid & 15; // 8 x 16 threads

    const float* Qbase = g_Qp + (size_t)(s * ARGS_PER) * D_MODEL;
    const float* Cbase = C    + (size_t)(s * CTX_PER + c0) * D_MODEL;

    float acc[4][4] = {};

    for (int k0 = 0; k0 < D_MODEL; k0 += 32) {
        // Q tile: 32 rows x 32 k = 256 float4, 2 per thread
        #pragma unroll
        for (int j = 0; j < 2; j++) {
            int id  = tid + j * 128;
            int row = id >> 3;              // 0..31
            int kq  = (id & 7) * 4;
            float4 v = *(const float4*)(Qbase + (size_t)row * D_MODEL + k0 + kq);
            Qs[kq + 0][row] = v.x; Qs[kq + 1][row] = v.y;
            Qs[kq + 2][row] = v.z; Qs[kq + 3][row] = v.w;
        }
        // C tile: 64 rows x 32 k = 512 float4, 4 per thread
        #pragma unroll
        for (int j = 0; j < 4; j++) {
            int id  = tid + j * 128;
            int row = id >> 3;              // 0..63
            int kq  = (id & 7) * 4;
            float4 v = *(const float4*)(Cbase + (size_t)row * D_MODEL + k0 + kq);
            Cs[kq + 0][row] = v.x; Cs[kq + 1][row] = v.y;
            Cs[kq + 2][row] = v.z; Cs[kq + 3][row] = v.w;
        }
        __syncthreads();
        #pragma unroll
        for (int k = 0; k < 32; k++) {
            float4 a = *(const float4*)&Qs[k][ty * 4];
            float4 c = *(const float4*)&Cs[k][tx * 4];
            float av[4] = {a.x, a.y, a.z, a.w};
            float cv[4] = {c.x, c.y, c.z, c.w};
            #pragma unroll
            for (int i = 0; i < 4; i++)
                #pragma unroll
                for (int jj = 0; jj < 4; jj++)
                    acc[i][jj] = fmaf(av[i], cv[jj], acc[i][jj]);
        }
        __syncthreads();
    }

    #pragma unroll
    for (int i = 0; i < 4; i++) {
        int rg = s * ARGS_PER + ty * 4 + i;      // global arg row
        float qb = g_qb[rg];
        size_t off = (size_t)rg * CTX_PER + c0 + tx * 4;
        float4 v = make_float4(acc[i][0] + qb, acc[i][1] + qb,
                               acc[i][2] + qb, acc[i][3] + qb);
        *(float4*)(out_logits + off) = v;
        if (out_rows) {
            float fr = (float)rg;
            *(float4*)(out_rows + off) = make_float4(fr, fr, fr, fr);
        }
    }
}

// ---------------------------------------------------------------------------
extern "C" void kernel_launch(void* const* d_in, const int* in_sizes, int n_in,
                              void* d_out, int out_size) {
    // Identify inputs by element count (arg_values and W share 65536 ->
    // disambiguated by order: arg_values precedes W in the input dict).
    const float* argv = nullptr;
    const float* ctxv = nullptr;
    const float* Wm   = nullptr;
    const float* bv   = nullptr;
    int seen_65536 = 0;
    for (int i = 0; i < n_in; i++) {
        long sz = in_sizes[i];
        if (sz == (long)N_CTX * D_MODEL) {
            ctxv = (const float*)d_in[i];
        } else if (sz == (long)N_ARGS * KEY_DIM) {   // == D_MODEL*KEY_DIM too
            if (seen_65536++ == 0) argv = (const float*)d_in[i];
            else                   Wm   = (const float*)d_in[i];
        } else if (sz == KEY_DIM) {
            bv = (const float*)d_in[i];
        }
    }

    float* out        = (float*)d_out;
    float* rows_out   = nullptr;
    float* logits_out = out;
    if (out_size >= 2 * P_TOT) {        // (rows, logits) concatenated
        rows_out   = out;
        logits_out = out + P_TOT;
    }

    qp_kernel<<<dim3(8, 8), 256>>>(argv, Wm);
    qb_kernel<<<2, 256>>>(argv, bv);
    logits_kernel<<<dim3(16, 16), 128>>>(ctxv, logits_out, rows_out);
}